// round 9
// baseline (speedup 1.0000x reference)
#include <cuda_runtime.h>
#include <cuda_fp16.h>

#define NN 100000
#define NE 1600000
#define NF 128
#define NC 64
#define SCB 98   // scan blocks: ceil(100000/1024)

// ---------------- device scratch (allocation-free) ----------------
__device__ unsigned long long g_pk[NN];   // bits[44+): edge count, bits[0:44): sum(w)*2^32
__device__ float  g_dinv[NN];
__device__ int    g_rowptr[NN + 1];       // CSR by target node
__device__ int    g_rank[NE];             // edge's slot within its target's list
__device__ volatile int g_flag[SCB];      // chained-scan flags (inclusive sum + 1)
__device__ int2   g_edge[NE];             // packed (src, weight-as-int)
__device__ uint2  g_h0[NN * 16];          // x @ W^T as half2 pairs (64 feats = 128B/row)
__device__ uint2  g_h1[NN * 16];          // after hop 1 (half)

// half<->float helpers
static __device__ __forceinline__ float2 u2f(unsigned v) {
    __half2 h = *reinterpret_cast<__half2*>(&v);
    return __half22float2(h);
}
static __device__ __forceinline__ unsigned f2u(float a, float b) {
    __half2 h = __floats2half2_rn(a, b);
    return *reinterpret_cast<unsigned*>(&h);
}
// packed fp32x2 FMA (Blackwell double-rate fp32)
static __device__ __forceinline__ void ffma2(unsigned long long& d,
                                             unsigned long long a,
                                             unsigned long long b) {
    asm("fma.rn.f32x2 %0, %1, %2, %0;" : "+l"(d) : "l"(a), "l"(b));
}
static __device__ __forceinline__ unsigned long long packff(float x) {
    unsigned long long r;
    asm("mov.b64 %0, {%1, %1};" : "=l"(r) : "f"(x));
    return r;
}

// ---------------- init ----------------
__global__ void k_init() {
    int i = blockIdx.x * blockDim.x + threadIdx.x;
    if (i < NN) g_pk[i] = (1ULL << 32);       // self-loop w=1.0 in 32.32 fixed point
    if (i < SCB) g_flag[i] = 0;
}

// ---------------- edge pass: ONE u64 atomic = count + weighted degree + rank ----
__global__ void k_edge1(const int* __restrict__ ei, const float* __restrict__ ew) {
    int e = blockIdx.x * blockDim.x + threadIdx.x;
    if (e >= NE) return;
    int c = ei[NE + e];                       // target node
    unsigned long long v = (1ULL << 44)
        + (unsigned long long)(ew[e] * 4294967296.0f);
    unsigned long long old = atomicAdd(&g_pk[c], v);
    g_rank[e] = (int)(old >> 44);             // unique slot within target's list
}

// ---------------- fused single-pass scan + dinv (chained lookback) --------------
__global__ void k_scan() {
    __shared__ int sh[256];
    __shared__ int s_prev;
    int t = threadIdx.x, b = blockIdx.x;
    int base = b * 1024 + t * 4;
    unsigned long long pk[4];
    int v[4], s = 0;
#pragma unroll
    for (int i = 0; i < 4; i++) {
        int idx = base + i;
        pk[i] = (idx < NN) ? g_pk[idx] : 0ULL;
        v[i] = (int)(pk[i] >> 44);
        s += v[i];
    }
    sh[t] = s;
    __syncthreads();
    for (int off = 1; off < 256; off <<= 1) {
        int add = (t >= off) ? sh[t - off] : 0;
        __syncthreads();
        sh[t] += add;
        __syncthreads();
    }
    int total = sh[255];
    if (t == 0) {
        int prev = 0;
        if (b > 0) {                       // all SCB blocks are co-resident (98 < 148 SMs)
            int f;
            while ((f = g_flag[b - 1]) == 0) {}
            prev = f - 1;
        }
        g_flag[b] = prev + total + 1;      // single packed word: value+1, 0 = not ready
        s_prev = prev;
    }
    __syncthreads();
    int ex = s_prev + sh[t] - s;
#pragma unroll
    for (int i = 0; i < 4; i++) {
        int idx = base + i;
        if (idx < NN) {
            g_rowptr[idx] = ex; ex += v[i];
            float deg = (float)(pk[i] & ((1ULL << 44) - 1)) * 2.3283064365386963e-10f;
            g_dinv[idx] = rsqrtf(deg);     // deg >= 1 always
        }
    }
    if (b == SCB - 1 && t == 0) g_rowptr[NN] = NE;
}

// ---------------- scatter edges into CSR, atomic-free ---------------------------
__global__ void k_scatter(const int* __restrict__ ei, const float* __restrict__ ew) {
    int e = blockIdx.x * blockDim.x + threadIdx.x;
    if (e >= NE) return;
    int r = ei[e];
    int c = ei[NE + e];
    int pos = g_rowptr[c] + g_rank[e];
    float wn = g_dinv[r] * ew[e] * g_dinv[c];
    g_edge[pos] = make_int2(r, __float_as_int(wn));
}

// ---------------- GEMM: y0 = x @ W^T -> half2, packed f32x2 FMA -----------------
// 128 nodes x 64 classes per block, 256 threads (16x16).
// Accumulators pair consecutive nodes: acc2[p][j] = (node 2p, node 2p+1) x class j.
#define XS_STRIDE 132
#define WS2_STRIDE 66
__global__ void k_gemm(const float* __restrict__ x, const float* __restrict__ W) {
    __shared__ float4 xs4[(32 * XS_STRIDE) / 4];
    __shared__ __align__(16) unsigned long long ws2[32 * WS2_STRIDE];
    float* xs = (float*)xs4;
    int tid = threadIdx.x;
    int tx = tid & 15;              // class group: classes tx*4 .. tx*4+3
    int ty = tid >> 4;              // node group:  nodes  ty*8 .. ty*8+7
    int n0 = blockIdx.x * 128;

    unsigned long long acc2[4][4];  // [node-pair][class], each = two fp32
#pragma unroll
    for (int p = 0; p < 4; p++)
#pragma unroll
        for (int j = 0; j < 4; j++) acc2[p][j] = 0ULL;

    for (int kt = 0; kt < NF; kt += 32) {
        // stage x tile transposed: xs[k][node]
        for (int i = tid; i < 128 * 32; i += 256) {
            int node = i >> 5, k = i & 31;
            int xr = n0 + node; if (xr >= NN) xr = NN - 1;
            xs[k * XS_STRIDE + node] = x[(size_t)xr * NF + kt + k];
        }
        // stage W tile transposed + duplicated: ws2[k][c] = (w,w)
        for (int i = tid; i < 64 * 32; i += 256) {
            int c = i >> 5, k = i & 31;
            ws2[k * WS2_STRIDE + c] = packff(W[c * NF + kt + k]);
        }
        __syncthreads();
#pragma unroll
        for (int k = 0; k < 32; k++) {
            const ulonglong2* xp = (const ulonglong2*)(xs + k * XS_STRIDE + ty * 8);
            ulonglong2 xa = xp[0], xb = xp[1];
            const ulonglong2* wp = (const ulonglong2*)(ws2 + k * WS2_STRIDE + tx * 4);
            ulonglong2 wA = wp[0], wB = wp[1];
            unsigned long long xpair[4] = {xa.x, xa.y, xb.x, xb.y};
            unsigned long long wd[4]    = {wA.x, wA.y, wB.x, wB.y};
#pragma unroll
            for (int p = 0; p < 4; p++) {
                ffma2(acc2[p][0], xpair[p], wd[0]);
                ffma2(acc2[p][1], xpair[p], wd[1]);
                ffma2(acc2[p][2], xpair[p], wd[2]);
                ffma2(acc2[p][3], xpair[p], wd[3]);
            }
        }
        __syncthreads();
    }
#pragma unroll
    for (int p = 0; p < 4; p++) {
        int nA = n0 + ty * 8 + 2 * p;
        int nB = nA + 1;
        float2 c0 = *reinterpret_cast<float2*>(&acc2[p][0]);
        float2 c1 = *reinterpret_cast<float2*>(&acc2[p][1]);
        float2 c2 = *reinterpret_cast<float2*>(&acc2[p][2]);
        float2 c3 = *reinterpret_cast<float2*>(&acc2[p][3]);
        if (nA < NN) g_h0[nA * 16 + tx] = make_uint2(f2u(c0.x, c1.x), f2u(c2.x, c3.x));
        if (nB < NN) g_h0[nB * 16 + tx] = make_uint2(f2u(c0.y, c1.y), f2u(c2.y, c3.y));
    }
}

// ---------------- SpMM hops (half rows, fp32 accumulate) ------------------------
// 16 threads/node; lane owns feats {4*lane .. 4*lane+3} = one uint2 (8B).
__global__ void k_hop1() {
    int gid = blockIdx.x * blockDim.x + threadIdx.x;
    int node = gid >> 4;
    if (node >= NN) return;
    int lane = gid & 15;

    int s = g_rowptr[node];
    int e = g_rowptr[node + 1];
    float dv = g_dinv[node];
    float sw = dv * dv;
    uint2 p = g_h0[node * 16 + lane];
    float2 f0 = u2f(p.x), f1 = u2f(p.y);
    float a0 = sw * f0.x, a1 = sw * f0.y, a2 = sw * f1.x, a3 = sw * f1.y;

#pragma unroll 2
    for (int i = s; i < e; i++) {
        int2 m = g_edge[i];
        float w = __int_as_float(m.y);
        uint2 q = g_h0[m.x * 16 + lane];
        float2 g0 = u2f(q.x), g1 = u2f(q.y);
        a0 = fmaf(w, g0.x, a0);
        a1 = fmaf(w, g0.y, a1);
        a2 = fmaf(w, g1.x, a2);
        a3 = fmaf(w, g1.y, a3);
    }
    g_h1[node * 16 + lane] = make_uint2(f2u(a0, a1), f2u(a2, a3));
}

__global__ void k_hop2(float4* __restrict__ out, const float4* __restrict__ bias) {
    int gid = blockIdx.x * blockDim.x + threadIdx.x;
    int node = gid >> 4;
    if (node >= NN) return;
    int lane = gid & 15;

    int s = g_rowptr[node];
    int e = g_rowptr[node + 1];
    float dv = g_dinv[node];
    float sw = dv * dv;
    uint2 p = g_h1[node * 16 + lane];
    float2 f0 = u2f(p.x), f1 = u2f(p.y);
    float a0 = sw * f0.x, a1 = sw * f0.y, a2 = sw * f1.x, a3 = sw * f1.y;

#pragma unroll 2
    for (int i = s; i < e; i++) {
        int2 m = g_edge[i];
        float w = __int_as_float(m.y);
        uint2 q = g_h1[m.x * 16 + lane];
        float2 g0 = u2f(q.x), g1 = u2f(q.y);
        a0 = fmaf(w, g0.x, a0);
        a1 = fmaf(w, g0.y, a1);
        a2 = fmaf(w, g1.x, a2);
        a3 = fmaf(w, g1.y, a3);
    }
    float4 b = bias[lane];
    out[node * 16 + lane] = make_float4(a0 + b.x, a1 + b.y, a2 + b.z, a3 + b.w);
}

// ---------------- launch: CSR build (default stream) || GEMM (side stream) ------
extern "C" void kernel_launch(void* const* d_in, const int* in_sizes, int n_in,
                              void* d_out, int out_size) {
    const float* x    = (const float*)d_in[0];
    const int*   ei   = (const int*)d_in[1];     // int32 edge_index [2, NE]
    const float* ew   = (const float*)d_in[2];
    const float* Wl   = (const float*)d_in[3];
    const float* bias = (const float*)d_in[4];
    float4* out = (float4*)d_out;

    const int NB_N  = (NN + 255) / 256;        // 391
    const int NB_E  = (NE + 255) / 256;        // 6250
    const int NB_H  = (NN * 16 + 255) / 256;   // 6250
    const int NB_G  = (NN + 127) / 128;        // 782

    cudaStream_t s2;
    cudaEvent_t evFork, evJoin;
    cudaStreamCreateWithFlags(&s2, cudaStreamNonBlocking);
    cudaEventCreateWithFlags(&evFork, cudaEventDisableTiming);
    cudaEventCreateWithFlags(&evJoin, cudaEventDisableTiming);

    // fork: GEMM independent of CSR build
    cudaEventRecord(evFork, 0);
    cudaStreamWaitEvent(s2, evFork, 0);
    k_gemm<<<NB_G, 256, 0, s2>>>(x, Wl);
    cudaEventRecord(evJoin, s2);

    // CSR build on default stream
    k_init<<<NB_N, 256>>>();
    k_edge1<<<NB_E, 256>>>(ei, ew);
    k_scan<<<SCB, 256>>>();
    k_scatter<<<NB_E, 256>>>(ei, ew);

    // join, then hops
    cudaStreamWaitEvent(0, evJoin, 0);
    k_hop1<<<NB_H, 256>>>();
    k_hop2<<<NB_H, 256>>>(out, (const float4*)bias);

    cudaStreamCaptureStatus st = cudaStreamCaptureStatusNone;
    cudaStreamIsCapturing(0, &st);
    if (st == cudaStreamCaptureStatusNone) {
        cudaEventDestroy(evFork);
        cudaEventDestroy(evJoin);
        cudaStreamDestroy(s2);
    }
}

// round 11
// speedup vs baseline: 1.1672x; 1.1672x over previous
#include <cuda_runtime.h>
#include <cuda_fp16.h>

#define NN 100000
#define NE 1600000
#define NF 128
#define NC 64
#define SCB 98   // scan blocks: ceil(100000/1024)

// ---------------- device scratch (allocation-free) ----------------
__device__ unsigned long long g_pk[NN];   // bits[44+): edge count, bits[0:44): sum(w)*2^32
__device__ float  g_dinv[NN];
__device__ int    g_rowptr[NN + 1];       // CSR by target node
__device__ int    g_rank[NE];             // edge's slot within its target's list
__device__ int    g_bsum[128];
__device__ int    g_boff[128];
__device__ int2   g_edge[NE];             // packed (src, weight-as-int)
__device__ uint2  g_h0[NN * 16];          // x @ W^T as half2 pairs (64 feats = 128B/row)
__device__ uint2  g_h1[NN * 16];          // after hop 1 (half)

// half<->float helpers
static __device__ __forceinline__ float2 u2f(unsigned v) {
    __half2 h = *reinterpret_cast<__half2*>(&v);
    return __half22float2(h);
}
static __device__ __forceinline__ unsigned f2u(float a, float b) {
    __half2 h = __floats2half2_rn(a, b);
    return *reinterpret_cast<unsigned*>(&h);
}
// packed fp32x2 FMA (Blackwell double-rate fp32)
static __device__ __forceinline__ void ffma2(unsigned long long& d,
                                             unsigned long long a,
                                             unsigned long long b) {
    asm("fma.rn.f32x2 %0, %1, %2, %0;" : "+l"(d) : "l"(a), "l"(b));
}
static __device__ __forceinline__ unsigned long long packff(float x) {
    unsigned long long r;
    asm("mov.b64 %0, {%1, %1};" : "=l"(r) : "f"(x));
    return r;
}

// ---------------- init ----------------
__global__ void k_init() {
    int i = blockIdx.x * blockDim.x + threadIdx.x;
    if (i < NN) g_pk[i] = (1ULL << 32);       // self-loop w=1.0 in 32.32 fixed point
    if (i == 0) g_rowptr[NN] = NE;
}

// ---------------- edge pass: ONE u64 atomic = count + weighted degree + rank ----
__global__ void k_edge1(const int* __restrict__ ei, const float* __restrict__ ew) {
    int e = blockIdx.x * blockDim.x + threadIdx.x;
    if (e >= NE) return;
    int c = ei[NE + e];                       // target node
    unsigned long long v = (1ULL << 44)
        + (unsigned long long)(ew[e] * 4294967296.0f);
    unsigned long long old = atomicAdd(&g_pk[c], v);
    g_rank[e] = (int)(old >> 44);             // unique slot within target's list
}

// ---------------- 3-kernel parallel scan (no cross-block serialization) ---------
__global__ void k_scan1() {
    __shared__ int sh[256];
    int t = threadIdx.x;
    int base = blockIdx.x * 1024 + t * 4;
    int v0 = 0, v1 = 0, v2 = 0, v3 = 0;
    if (base + 0 < NN) v0 = (int)(g_pk[base + 0] >> 44);
    if (base + 1 < NN) v1 = (int)(g_pk[base + 1] >> 44);
    if (base + 2 < NN) v2 = (int)(g_pk[base + 2] >> 44);
    if (base + 3 < NN) v3 = (int)(g_pk[base + 3] >> 44);
    int s = v0 + v1 + v2 + v3;
    sh[t] = s;
    __syncthreads();
    for (int off = 1; off < 256; off <<= 1) {
        int add = (t >= off) ? sh[t - off] : 0;
        __syncthreads();
        sh[t] += add;
        __syncthreads();
    }
    int ex = sh[t] - s;
    if (base + 0 < NN) g_rowptr[base + 0] = ex;
    if (base + 1 < NN) g_rowptr[base + 1] = ex + v0;
    if (base + 2 < NN) g_rowptr[base + 2] = ex + v0 + v1;
    if (base + 3 < NN) g_rowptr[base + 3] = ex + v0 + v1 + v2;
    if (t == 255) g_bsum[blockIdx.x] = sh[255];
}

__global__ void k_scan2(int nb) {
    __shared__ int sh[128];
    int t = threadIdx.x;
    int v = (t < nb) ? g_bsum[t] : 0;
    sh[t] = v;
    __syncthreads();
    for (int off = 1; off < 128; off <<= 1) {
        int add = (t >= off) ? sh[t - off] : 0;
        __syncthreads();
        sh[t] += add;
        __syncthreads();
    }
    if (t < nb) g_boff[t] = sh[t] - v;
}

// scan3: finalize rowptr + decode dinv from packed degree
__global__ void k_scan3() {
    int off = g_boff[blockIdx.x];
    int base = blockIdx.x * 1024 + threadIdx.x * 4;
#pragma unroll
    for (int i = 0; i < 4; i++) {
        int idx = base + i;
        if (idx < NN) {
            g_rowptr[idx] += off;
            float deg = (float)(g_pk[idx] & ((1ULL << 44) - 1)) * 2.3283064365386963e-10f;
            g_dinv[idx] = rsqrtf(deg);     // deg >= 1 always
        }
    }
}

// ---------------- scatter edges into CSR, atomic-free ---------------------------
__global__ void k_scatter(const int* __restrict__ ei, const float* __restrict__ ew) {
    int e = blockIdx.x * blockDim.x + threadIdx.x;
    if (e >= NE) return;
    int r = ei[e];
    int c = ei[NE + e];
    int pos = g_rowptr[c] + g_rank[e];
    float wn = g_dinv[r] * ew[e] * g_dinv[c];
    g_edge[pos] = make_int2(r, __float_as_int(wn));
}

// ---------------- GEMM: y0 = x @ W^T -> half2, packed f32x2 FMA -----------------
#define XS_STRIDE 132
#define WS2_STRIDE 66
__global__ void k_gemm(const float* __restrict__ x, const float* __restrict__ W) {
    __shared__ float4 xs4[(32 * XS_STRIDE) / 4];
    __shared__ __align__(16) unsigned long long ws2[32 * WS2_STRIDE];
    float* xs = (float*)xs4;
    int tid = threadIdx.x;
    int tx = tid & 15;              // class group: classes tx*4 .. tx*4+3
    int ty = tid >> 4;              // node group:  nodes  ty*8 .. ty*8+7
    int n0 = blockIdx.x * 128;

    unsigned long long acc2[4][4];  // [node-pair][class], each = two fp32
#pragma unroll
    for (int p = 0; p < 4; p++)
#pragma unroll
        for (int j = 0; j < 4; j++) acc2[p][j] = 0ULL;

    for (int kt = 0; kt < NF; kt += 32) {
        for (int i = tid; i < 128 * 32; i += 256) {
            int node = i >> 5, k = i & 31;
            int xr = n0 + node; if (xr >= NN) xr = NN - 1;
            xs[k * XS_STRIDE + node] = x[(size_t)xr * NF + kt + k];
        }
        for (int i = tid; i < 64 * 32; i += 256) {
            int c = i >> 5, k = i & 31;
            ws2[k * WS2_STRIDE + c] = packff(W[c * NF + kt + k]);
        }
        __syncthreads();
#pragma unroll
        for (int k = 0; k < 32; k++) {
            const ulonglong2* xp = (const ulonglong2*)(xs + k * XS_STRIDE + ty * 8);
            ulonglong2 xa = xp[0], xb = xp[1];
            const ulonglong2* wp = (const ulonglong2*)(ws2 + k * WS2_STRIDE + tx * 4);
            ulonglong2 wA = wp[0], wB = wp[1];
            unsigned long long xpair[4] = {xa.x, xa.y, xb.x, xb.y};
            unsigned long long wd[4]    = {wA.x, wA.y, wB.x, wB.y};
#pragma unroll
            for (int p = 0; p < 4; p++) {
                ffma2(acc2[p][0], xpair[p], wd[0]);
                ffma2(acc2[p][1], xpair[p], wd[1]);
                ffma2(acc2[p][2], xpair[p], wd[2]);
                ffma2(acc2[p][3], xpair[p], wd[3]);
            }
        }
        __syncthreads();
    }
#pragma unroll
    for (int p = 0; p < 4; p++) {
        int nA = n0 + ty * 8 + 2 * p;
        int nB = nA + 1;
        float2 c0 = *reinterpret_cast<float2*>(&acc2[p][0]);
        float2 c1 = *reinterpret_cast<float2*>(&acc2[p][1]);
        float2 c2 = *reinterpret_cast<float2*>(&acc2[p][2]);
        float2 c3 = *reinterpret_cast<float2*>(&acc2[p][3]);
        if (nA < NN) g_h0[nA * 16 + tx] = make_uint2(f2u(c0.x, c1.x), f2u(c2.x, c3.x));
        if (nB < NN) g_h0[nB * 16 + tx] = make_uint2(f2u(c0.y, c1.y), f2u(c2.y, c3.y));
    }
}

// ---------------- SpMM hops (half rows, fp32 accumulate) ------------------------
__global__ void k_hop1() {
    int gid = blockIdx.x * blockDim.x + threadIdx.x;
    int node = gid >> 4;
    if (node >= NN) return;
    int lane = gid & 15;

    int s = g_rowptr[node];
    int e = g_rowptr[node + 1];
    float dv = g_dinv[node];
    float sw = dv * dv;
    uint2 p = g_h0[node * 16 + lane];
    float2 f0 = u2f(p.x), f1 = u2f(p.y);
    float a0 = sw * f0.x, a1 = sw * f0.y, a2 = sw * f1.x, a3 = sw * f1.y;

#pragma unroll 2
    for (int i = s; i < e; i++) {
        int2 m = g_edge[i];
        float w = __int_as_float(m.y);
        uint2 q = g_h0[m.x * 16 + lane];
        float2 g0 = u2f(q.x), g1 = u2f(q.y);
        a0 = fmaf(w, g0.x, a0);
        a1 = fmaf(w, g0.y, a1);
        a2 = fmaf(w, g1.x, a2);
        a3 = fmaf(w, g1.y, a3);
    }
    g_h1[node * 16 + lane] = make_uint2(f2u(a0, a1), f2u(a2, a3));
}

__global__ void k_hop2(float4* __restrict__ out, const float4* __restrict__ bias) {
    int gid = blockIdx.x * blockDim.x + threadIdx.x;
    int node = gid >> 4;
    if (node >= NN) return;
    int lane = gid & 15;

    int s = g_rowptr[node];
    int e = g_rowptr[node + 1];
    float dv = g_dinv[node];
    float sw = dv * dv;
    uint2 p = g_h1[node * 16 + lane];
    float2 f0 = u2f(p.x), f1 = u2f(p.y);
    float a0 = sw * f0.x, a1 = sw * f0.y, a2 = sw * f1.x, a3 = sw * f1.y;

#pragma unroll 2
    for (int i = s; i < e; i++) {
        int2 m = g_edge[i];
        float w = __int_as_float(m.y);
        uint2 q = g_h1[m.x * 16 + lane];
        float2 g0 = u2f(q.x), g1 = u2f(q.y);
        a0 = fmaf(w, g0.x, a0);
        a1 = fmaf(w, g0.y, a1);
        a2 = fmaf(w, g1.x, a2);
        a3 = fmaf(w, g1.y, a3);
    }
    float4 b = bias[lane];
    out[node * 16 + lane] = make_float4(a0 + b.x, a1 + b.y, a2 + b.z, a3 + b.w);
}

// ---------------- launch: CSR build (default stream) || GEMM (side stream) ------
extern "C" void kernel_launch(void* const* d_in, const int* in_sizes, int n_in,
                              void* d_out, int out_size) {
    const float* x    = (const float*)d_in[0];
    const int*   ei   = (const int*)d_in[1];     // int32 edge_index [2, NE]
    const float* ew   = (const float*)d_in[2];
    const float* Wl   = (const float*)d_in[3];
    const float* bias = (const float*)d_in[4];
    float4* out = (float4*)d_out;

    const int NB_N  = (NN + 255) / 256;        // 391
    const int NB_E  = (NE + 255) / 256;        // 6250
    const int NB_H  = (NN * 16 + 255) / 256;   // 6250
    const int NB_G  = (NN + 127) / 128;        // 782

    cudaStream_t s2;
    cudaEvent_t evFork, evJoin;
    cudaStreamCreateWithFlags(&s2, cudaStreamNonBlocking);
    cudaEventCreateWithFlags(&evFork, cudaEventDisableTiming);
    cudaEventCreateWithFlags(&evJoin, cudaEventDisableTiming);

    // fork: GEMM independent of CSR build
    cudaEventRecord(evFork, 0);
    cudaStreamWaitEvent(s2, evFork, 0);
    k_gemm<<<NB_G, 256, 0, s2>>>(x, Wl);
    cudaEventRecord(evJoin, s2);

    // CSR build on default stream
    k_init<<<NB_N, 256>>>();
    k_edge1<<<NB_E, 256>>>(ei, ew);
    k_scan1<<<SCB, 256>>>();
    k_scan2<<<1, 128>>>(SCB);
    k_scan3<<<SCB, 256>>>();
    k_scatter<<<NB_E, 256>>>(ei, ew);

    // join, then hops
    cudaStreamWaitEvent(0, evJoin, 0);
    k_hop1<<<NB_H, 256>>>();
    k_hop2<<<NB_H, 256>>>(out, (const float4*)bias);

    cudaStreamCaptureStatus st = cudaStreamCaptureStatusNone;
    cudaStreamIsCapturing(0, &st);
    if (st == cudaStreamCaptureStatusNone) {
        cudaEventDestroy(evFork);
        cudaEventDestroy(evJoin);
        cudaStreamDestroy(s2);
    }
}

// round 12
// speedup vs baseline: 1.4674x; 1.2572x over previous
#include <cuda_runtime.h>
#include <cuda_fp16.h>

#define NN 100000
#define NE 1600000
#define NF 128
#define NC 64
#define SCB 98   // scan blocks: ceil(100000/1024)

// ---------------- device scratch (allocation-free) ----------------
__device__ unsigned long long g_pk[NN];   // bits[44+): edge count, bits[0:44): sum(w)*2^32
__device__ float  g_dinv[NN];
__device__ int    g_cnt[NN];              // scatter cursor
__device__ int    g_rowptr[NN + 1];       // CSR by target node
__device__ int    g_bsum[128];
__device__ int    g_boff[128];
__device__ int2   g_edge[NE];             // packed (src, weight-as-int)
__device__ uint2  g_h0[NN * 16];          // x @ W^T as half2 pairs (64 feats = 128B/row)
__device__ uint2  g_h1[NN * 16];          // after hop 1 (half)

// half<->float helpers
static __device__ __forceinline__ float2 u2f(unsigned v) {
    __half2 h = *reinterpret_cast<__half2*>(&v);
    return __half22float2(h);
}
static __device__ __forceinline__ unsigned f2u(float a, float b) {
    __half2 h = __floats2half2_rn(a, b);
    return *reinterpret_cast<unsigned*>(&h);
}

// ---------------- init: pk = self-loop weight 1.0 (count 0) ----------------
__global__ void k_init() {
    int i = blockIdx.x * blockDim.x + threadIdx.x;
    if (i < NN) g_pk[i] = (1ULL << 32);       // w=1.0 in 32.32 fixed point
    if (i == 0) g_rowptr[NN] = NE;
}

// ---------------- edge pass: ONE u64 atomic = count + weighted degree ----------
__global__ void k_edge1(const int* __restrict__ ei, const float* __restrict__ ew) {
    int e = blockIdx.x * blockDim.x + threadIdx.x;
    if (e >= NE) return;
    int c = ei[NE + e];                       // target node
    unsigned long long v = (1ULL << 44)
        + (unsigned long long)(ew[e] * 4294967296.0f);
    atomicAdd(&g_pk[c], v);
}

// ---------------- 3-kernel parallel scan ----------------------------------------
__global__ void k_scan1() {
    __shared__ int sh[256];
    int t = threadIdx.x;
    int base = blockIdx.x * 1024 + t * 4;
    int v0 = 0, v1 = 0, v2 = 0, v3 = 0;
    if (base + 0 < NN) v0 = (int)(g_pk[base + 0] >> 44);
    if (base + 1 < NN) v1 = (int)(g_pk[base + 1] >> 44);
    if (base + 2 < NN) v2 = (int)(g_pk[base + 2] >> 44);
    if (base + 3 < NN) v3 = (int)(g_pk[base + 3] >> 44);
    int s = v0 + v1 + v2 + v3;
    sh[t] = s;
    __syncthreads();
    for (int off = 1; off < 256; off <<= 1) {
        int add = (t >= off) ? sh[t - off] : 0;
        __syncthreads();
        sh[t] += add;
        __syncthreads();
    }
    int ex = sh[t] - s;
    if (base + 0 < NN) g_rowptr[base + 0] = ex;
    if (base + 1 < NN) g_rowptr[base + 1] = ex + v0;
    if (base + 2 < NN) g_rowptr[base + 2] = ex + v0 + v1;
    if (base + 3 < NN) g_rowptr[base + 3] = ex + v0 + v1 + v2;
    if (t == 255) g_bsum[blockIdx.x] = sh[255];
}

__global__ void k_scan2(int nb) {
    __shared__ int sh[128];
    int t = threadIdx.x;
    int v = (t < nb) ? g_bsum[t] : 0;
    sh[t] = v;
    __syncthreads();
    for (int off = 1; off < 128; off <<= 1) {
        int add = (t >= off) ? sh[t - off] : 0;
        __syncthreads();
        sh[t] += add;
        __syncthreads();
    }
    if (t < nb) g_boff[t] = sh[t] - v;
}

// scan3: finalize rowptr, init cursor, decode dinv from packed degree
__global__ void k_scan3() {
    int off = g_boff[blockIdx.x];
    int base = blockIdx.x * 1024 + threadIdx.x * 4;
#pragma unroll
    for (int i = 0; i < 4; i++) {
        int idx = base + i;
        if (idx < NN) {
            int v = g_rowptr[idx] + off;
            g_rowptr[idx] = v;
            g_cnt[idx] = v;
            float deg = (float)(g_pk[idx] & ((1ULL << 44) - 1)) * 2.3283064365386963e-10f;
            g_dinv[idx] = rsqrtf(deg);     // deg >= 1 always
        }
    }
}

// ---------------- scatter edges into CSR with normalized weights (packed) -------
__global__ void k_scatter(const int* __restrict__ ei, const float* __restrict__ ew) {
    int e = blockIdx.x * blockDim.x + threadIdx.x;
    if (e >= NE) return;
    int r = ei[e];
    int c = ei[NE + e];
    int pos = atomicAdd(&g_cnt[c], 1);
    float wn = g_dinv[r] * ew[e] * g_dinv[c];
    g_edge[pos] = make_int2(r, __float_as_int(wn));
}

// ---------------- GEMM: y0 = x @ W^T -> half2, fp16 tensor cores ----------------
// 64 nodes x 64 classes per block, 128 threads (4 warps), each warp 16 rows.
// mma.sync.m16n8k16 f32.f16.f16.f32; manual fragment loads from padded smem.
#define HS 136   // smem row stride in halfs (128 + 8 pad -> conflict-free frags)
__global__ void k_gemmT(const float* __restrict__ x, const float* __restrict__ W) {
    __shared__ __half xs[64 * HS];
    __shared__ __half wsh[64 * HS];
    int tid = threadIdx.x;
    int warp = tid >> 5, lane = tid & 31;
    int g = lane >> 2, tg = lane & 3;
    int n0 = blockIdx.x * 64;

    // stage X tile (64 rows x 128) fp32 -> half, float4 granularity
    for (int i = tid; i < 64 * 32; i += 128) {
        int r = i >> 5, q = i & 31;
        int xr = n0 + r; if (xr >= NN) xr = NN - 1;
        float4 v = ((const float4*)(x + (size_t)xr * NF))[q];
        __half2* dst = (__half2*)&xs[r * HS + q * 4];
        dst[0] = __floats2half2_rn(v.x, v.y);
        dst[1] = __floats2half2_rn(v.z, v.w);
    }
    // stage W (64 x 128) fp32 -> half
    for (int i = tid; i < 64 * 32; i += 128) {
        int r = i >> 5, q = i & 31;
        float4 v = ((const float4*)(W + (size_t)r * NF))[q];
        __half2* dst = (__half2*)&wsh[r * HS + q * 4];
        dst[0] = __floats2half2_rn(v.x, v.y);
        dst[1] = __floats2half2_rn(v.z, v.w);
    }
    __syncthreads();

    int row0 = warp * 16;
    float c[8][4];
#pragma unroll
    for (int j = 0; j < 8; j++)
#pragma unroll
        for (int q = 0; q < 4; q++) c[j][q] = 0.0f;

#pragma unroll
    for (int ks = 0; ks < 128; ks += 16) {
        unsigned a0 = *(const unsigned*)&xs[(row0 + g) * HS + ks + tg * 2];
        unsigned a1 = *(const unsigned*)&xs[(row0 + g + 8) * HS + ks + tg * 2];
        unsigned a2 = *(const unsigned*)&xs[(row0 + g) * HS + ks + 8 + tg * 2];
        unsigned a3 = *(const unsigned*)&xs[(row0 + g + 8) * HS + ks + 8 + tg * 2];
#pragma unroll
        for (int j = 0; j < 8; j++) {
            unsigned b0 = *(const unsigned*)&wsh[(j * 8 + g) * HS + ks + tg * 2];
            unsigned b1 = *(const unsigned*)&wsh[(j * 8 + g) * HS + ks + 8 + tg * 2];
            asm volatile(
                "mma.sync.aligned.m16n8k16.row.col.f32.f16.f16.f32 "
                "{%0,%1,%2,%3}, {%4,%5,%6,%7}, {%8,%9}, {%0,%1,%2,%3};"
                : "+f"(c[j][0]), "+f"(c[j][1]), "+f"(c[j][2]), "+f"(c[j][3])
                : "r"(a0), "r"(a1), "r"(a2), "r"(a3), "r"(b0), "r"(b1));
        }
    }

    // epilogue: D[row][n], c0,c1 = (row0+g, 2tg/2tg+1 of n-tile j); c2,c3 = row+8
    unsigned* h0 = (unsigned*)g_h0;   // flat: [node][32] half2-words
    int nA = n0 + row0 + g;
    int nB = nA + 8;
#pragma unroll
    for (int j = 0; j < 8; j++) {
        if (nA < NN) h0[nA * 32 + j * 4 + tg] = f2u(c[j][0], c[j][1]);
        if (nB < NN) h0[nB * 32 + j * 4 + tg] = f2u(c[j][2], c[j][3]);
    }
}

// ---------------- SpMM hops (half rows, fp32 accumulate) ------------------------
__global__ void k_hop1() {
    int gid = blockIdx.x * blockDim.x + threadIdx.x;
    int node = gid >> 4;
    if (node >= NN) return;
    int lane = gid & 15;

    int s = g_rowptr[node];
    int e = g_rowptr[node + 1];
    float dv = g_dinv[node];
    float sw = dv * dv;
    uint2 p = g_h0[node * 16 + lane];
    float2 f0 = u2f(p.x), f1 = u2f(p.y);
    float a0 = sw * f0.x, a1 = sw * f0.y, a2 = sw * f1.x, a3 = sw * f1.y;

#pragma unroll 2
    for (int i = s; i < e; i++) {
        int2 m = g_edge[i];
        float w = __int_as_float(m.y);
        uint2 q = g_h0[m.x * 16 + lane];
        float2 g0 = u2f(q.x), g1 = u2f(q.y);
        a0 = fmaf(w, g0.x, a0);
        a1 = fmaf(w, g0.y, a1);
        a2 = fmaf(w, g1.x, a2);
        a3 = fmaf(w, g1.y, a3);
    }
    g_h1[node * 16 + lane] = make_uint2(f2u(a0, a1), f2u(a2, a3));
}

__global__ void k_hop2(float4* __restrict__ out, const float4* __restrict__ bias) {
    int gid = blockIdx.x * blockDim.x + threadIdx.x;
    int node = gid >> 4;
    if (node >= NN) return;
    int lane = gid & 15;

    int s = g_rowptr[node];
    int e = g_rowptr[node + 1];
    float dv = g_dinv[node];
    float sw = dv * dv;
    uint2 p = g_h1[node * 16 + lane];
    float2 f0 = u2f(p.x), f1 = u2f(p.y);
    float a0 = sw * f0.x, a1 = sw * f0.y, a2 = sw * f1.x, a3 = sw * f1.y;

#pragma unroll 2
    for (int i = s; i < e; i++) {
        int2 m = g_edge[i];
        float w = __int_as_float(m.y);
        uint2 q = g_h1[m.x * 16 + lane];
        float2 g0 = u2f(q.x), g1 = u2f(q.y);
        a0 = fmaf(w, g0.x, a0);
        a1 = fmaf(w, g0.y, a1);
        a2 = fmaf(w, g1.x, a2);
        a3 = fmaf(w, g1.y, a3);
    }
    float4 b = bias[lane];
    out[node * 16 + lane] = make_float4(a0 + b.x, a1 + b.y, a2 + b.z, a3 + b.w);
}

// ---------------- launch: CSR build (default stream) || GEMM (side stream) ------
extern "C" void kernel_launch(void* const* d_in, const int* in_sizes, int n_in,
                              void* d_out, int out_size) {
    const float* x    = (const float*)d_in[0];
    const int*   ei   = (const int*)d_in[1];     // int32 edge_index [2, NE]
    const float* ew   = (const float*)d_in[2];
    const float* Wl   = (const float*)d_in[3];
    const float* bias = (const float*)d_in[4];
    float4* out = (float4*)d_out;

    const int NB_N  = (NN + 255) / 256;        // 391
    const int NB_E  = (NE + 255) / 256;        // 6250
    const int NB_H  = (NN * 16 + 255) / 256;   // 6250
    const int NB_G  = (NN + 63) / 64;          // 1563

    cudaStream_t s2;
    cudaEvent_t evFork, evJoin;
    cudaStreamCreateWithFlags(&s2, cudaStreamNonBlocking);
    cudaEventCreateWithFlags(&evFork, cudaEventDisableTiming);
    cudaEventCreateWithFlags(&evJoin, cudaEventDisableTiming);

    // fork: GEMM independent of CSR build
    cudaEventRecord(evFork, 0);
    cudaStreamWaitEvent(s2, evFork, 0);
    k_gemmT<<<NB_G, 128, 0, s2>>>(x, Wl);
    cudaEventRecord(evJoin, s2);

    // CSR build on default stream
    k_init<<<NB_N, 256>>>();
    k_edge1<<<NB_E, 256>>>(ei, ew);
    k_scan1<<<SCB, 256>>>();
    k_scan2<<<1, 128>>>(SCB);
    k_scan3<<<SCB, 256>>>();
    k_scatter<<<NB_E, 256>>>(ei, ew);

    // join, then hops
    cudaStreamWaitEvent(0, evJoin, 0);
    k_hop1<<<NB_H, 256>>>();
    k_hop2<<<NB_H, 256>>>(out, (const float4*)bias);

    cudaStreamCaptureStatus st = cudaStreamCaptureStatusNone;
    cudaStreamIsCapturing(0, &st);
    if (st == cudaStreamCaptureStatusNone) {
        cudaEventDestroy(evFork);
        cudaEventDestroy(evJoin);
        cudaStreamDestroy(s2);
    }
}